// round 11
// baseline (speedup 1.0000x reference)
#include <cuda_runtime.h>
#include <cuda_fp16.h>
#include <cstdint>
#include <cstddef>

// ---------------------------------------------------------------------------
// RNNQNetworkZeroState, sm_103. fp16 m16n8k16 mma.sync, fp32 accumulate.
//   conv:  x,W1,W2,W3 fp32 -> fp16 (rn);  bsum = b_ih + b_hh
//   GEMM1: xh[M,1024]  @ W1h^T + b_init -> relu -> g_h   (half)
//   GEMM2: g_h[M,2048] @ W2h^T + bsum   -> relu -> g_mid (half)
//   GEMM3: g_mid       @ W3h^T + b_final -> out (float)
// GEMM: tile 128x128 (8 warps, 64x32 warp tiles, 2 CTAs/SM), BK=64 halves,
// 3-stage cp.async pipeline, R4 ordering (PRODUCE i+2 -> wait_group 2 ->
// sync -> compute -> sync), B-fragment double buffering, K templated.
// This round: conv pre-passes one-shot exact-size grids (they were
// latency-bound at occ 38% / issue 5.4%).
// ---------------------------------------------------------------------------

#define BM 128
#define BN 128
#define BKH 64                 // halves per k-chunk = 128 bytes/row
#define NSTAGE 3
#define A_STAGE 16384          // 128 rows x 128 B
#define B_STAGE 16384
#define STAGE_BYTES (A_STAGE + B_STAGE)
#define SMEM_TOTAL (NSTAGE * STAGE_BYTES)   // 98304 B
#define NTHREADS 256

static constexpr size_t M_TOK = 32768;

// Scratch (allocation-free rule: __device__ globals).
__device__ __align__(16) __half g_xh  [M_TOK * 1024];
__device__ __align__(16) __half g_h   [M_TOK * 2048];
__device__ __align__(16) __half g_mid [M_TOK * 2048];
__device__ __align__(16) __half g_w1  [2048 * 1024];
__device__ __align__(16) __half g_w2  [2048 * 2048];
__device__ __align__(16) __half g_w3  [1024 * 2048];
__device__ __align__(16) float  g_bsum[2048];

#define SWZ(o) ((o) ^ (((o) >> 3) & 0x70))

__device__ __forceinline__ uint32_t s2u(const void* p) {
    uint32_t a;
    asm("{ .reg .u64 t; cvta.to.shared.u64 t, %1; cvt.u32.u64 %0, t; }"
        : "=r"(a) : "l"(p));
    return a;
}
__device__ __forceinline__ void cp16(uint32_t s, const void* g) {
    asm volatile("cp.async.cg.shared.global [%0], [%1], 16;" :: "r"(s), "l"(g));
}
__device__ __forceinline__ void ldsm4(uint32_t (&r)[4], uint32_t addr) {
    asm volatile("ldmatrix.sync.aligned.m8n8.x4.shared.b16 {%0,%1,%2,%3}, [%4];"
                 : "=r"(r[0]), "=r"(r[1]), "=r"(r[2]), "=r"(r[3]) : "r"(addr));
}
__device__ __forceinline__ void mma_f16(float (&d)[4], const uint32_t (&a)[4],
                                        uint32_t b0, uint32_t b1) {
    asm volatile(
        "mma.sync.aligned.m16n8k16.row.col.f32.f16.f16.f32 "
        "{%0,%1,%2,%3}, {%4,%5,%6,%7}, {%8,%9}, {%0,%1,%2,%3};"
        : "+f"(d[0]), "+f"(d[1]), "+f"(d[2]), "+f"(d[3])
        : "r"(a[0]), "r"(a[1]), "r"(a[2]), "r"(a[3]), "r"(b0), "r"(b1));
}

__device__ __forceinline__ void store2(__half* C, long off, float v0, float v1) {
    *reinterpret_cast<__half2*>(C + off) =
        __halves2half2(__float2half_rn(v0), __float2half_rn(v1));
}
__device__ __forceinline__ void store2(float* C, long off, float v0, float v1) {
    *reinterpret_cast<float2*>(C + off) = make_float2(v0, v1);
}

template <int K, bool RELU, typename TOUT>
__global__ void __launch_bounds__(NTHREADS, 2)
gemm_f16(const __half* __restrict__ A,     // [M,K] row-major
         const __half* __restrict__ W,     // [N,K] row-major
         const float* __restrict__ bias,   // [N]
         TOUT* __restrict__ C,             // [M,N]
         int Nn)
{
    extern __shared__ char smem[];
    const uint32_t sb = s2u(smem);

    const int tid  = threadIdx.x;
    const int lane = tid & 31;
    const int wid  = tid >> 5;
    const int wr   = wid >> 2;   // 0..1 : 64-row slab
    const int wc   = wid & 3;    // 0..3 : 32-col slab

    const long bm = (long)blockIdx.y * BM;
    const long bn = (long)blockIdx.x * BN;
    constexpr int nchunk = K / BKH;

    // ---- global->shared mapping: 8 threads/row (16B each), 4 rows/thread ----
    const int lrow = tid >> 3;         // 0..31
    const int lc16 = (tid & 7) * 16;   // byte col in 128B row
    const __half* Abase = A + (bm + lrow) * (long)K + (tid & 7) * 8;
    const __half* Bbase = W + (bn + lrow) * (long)K + (tid & 7) * 8;
    constexpr long rstep = 32L * K;    // 32-row advance (halves)

    uint32_t stoff[4];
    #pragma unroll
    for (int k = 0; k < 4; k++)
        stoff[k] = SWZ((uint32_t)((lrow + 32 * k) * 128 + lc16));

    // ---- ldmatrix address components ----
    const uint32_t xorv = (uint32_t)(lane & 7) << 4;           // swizzle xor
    uint32_t arow[4], brow[2];
    #pragma unroll
    for (int mt = 0; mt < 4; mt++)
        arow[mt] = (uint32_t)((wr * 64 + mt * 16 + (lane & 15)) * 128);
    #pragma unroll
    for (int p = 0; p < 2; p++)
        brow[p] = (uint32_t)((wc * 32 + p * 16 + (lane & 7) + ((lane >> 4) & 1) * 8) * 128);
    const uint32_t kA16 = ((lane >> 4) & 1) * 16;   // A: k+8 for lanes 16-31
    const uint32_t kB16 = ((lane >> 3) & 1) * 16;   // B: k+8 for lanes 8-15,24-31

    // per-ks k-byte offsets (post-swizzle xor folded in)
    uint32_t kbA[4], kbB[4];
    #pragma unroll
    for (int ks = 0; ks < 4; ks++) {
        kbA[ks] = ((uint32_t)(ks * 32) + kA16) ^ xorv;
        kbB[ks] = ((uint32_t)(ks * 32) + kB16) ^ xorv;
    }

    float acc[4][4][4];
    #pragma unroll
    for (int mt = 0; mt < 4; mt++)
        #pragma unroll
        for (int nt = 0; nt < 4; nt++)
            #pragma unroll
            for (int r = 0; r < 4; r++) acc[mt][nt][r] = 0.0f;

    #define PRODUCE(slot, kc)                                                   \
        do {                                                                    \
            const uint32_t _as = sb + (slot) * STAGE_BYTES;                     \
            const uint32_t _bs = _as + A_STAGE;                                 \
            const __half* _ap = Abase + (long)(kc) * BKH;                       \
            const __half* _bp = Bbase + (long)(kc) * BKH;                       \
            _Pragma("unroll")                                                   \
            for (int k = 0; k < 4; k++) {                                       \
                cp16(_as + stoff[k], _ap + k * rstep);                          \
                cp16(_bs + stoff[k], _bp + k * rstep);                          \
            }                                                                   \
            asm volatile("cp.async.commit_group;");                             \
        } while (0)

    // prologue: chunks 0,1 into slots 0,1
    PRODUCE(0, 0);
    PRODUCE(1, 1);

    int slot = 0, pslot = 2;
    #pragma unroll 3
    for (int i = 0; i < nchunk; i++) {
        if (i + 2 < nchunk) {
            PRODUCE(pslot, i + 2);
            asm volatile("cp.async.wait_group 2;");
        } else if (i + 1 < nchunk) {
            asm volatile("cp.async.wait_group 1;");
        } else {
            asm volatile("cp.async.wait_group 0;");
        }
        __syncthreads();

        const uint32_t stA = sb + slot * STAGE_BYTES;
        const uint32_t stB = stA + A_STAGE;

        // B-fragment double buffer: prefetch ks+1's B during ks's HMMA block.
        uint32_t bf[2][2][4];
        ldsm4(bf[0][0], stB + brow[0] + kbB[0]);
        ldsm4(bf[0][1], stB + brow[1] + kbB[0]);

        #pragma unroll
        for (int ks = 0; ks < 4; ks++) {
            const int cur = ks & 1;
            const int nxt = cur ^ 1;
            uint32_t af[4][4];
            #pragma unroll
            for (int mt = 0; mt < 4; mt++)
                ldsm4(af[mt], stA + arow[mt] + kbA[ks]);
            if (ks < 3) {
                ldsm4(bf[nxt][0], stB + brow[0] + kbB[ks + 1]);
                ldsm4(bf[nxt][1], stB + brow[1] + kbB[ks + 1]);
            }
            #pragma unroll
            for (int mt = 0; mt < 4; mt++)
                #pragma unroll
                for (int nt = 0; nt < 4; nt++)
                    mma_f16(acc[mt][nt], af[mt],
                            bf[cur][nt >> 1][(nt & 1) * 2],
                            bf[cur][nt >> 1][(nt & 1) * 2 + 1]);
        }
        __syncthreads();
        slot  = (slot  == NSTAGE - 1) ? 0 : slot + 1;
        pslot = (pslot == NSTAGE - 1) ? 0 : pslot + 1;
    }
    #undef PRODUCE

    // ---- epilogue ----
    const int gid = lane >> 2;     // row in 8-row group
    const int tin = lane & 3;      // column pair
    #pragma unroll
    for (int nt = 0; nt < 4; nt++) {
        const long n0 = bn + wc * 32 + nt * 8 + tin * 2;
        const float bv0 = bias[n0];
        const float bv1 = bias[n0 + 1];
        #pragma unroll
        for (int mt = 0; mt < 4; mt++) {
            const long m0 = bm + wr * 64 + mt * 16 + gid;
            float v0 = acc[mt][nt][0] + bv0;
            float v1 = acc[mt][nt][1] + bv1;
            float v2 = acc[mt][nt][2] + bv0;
            float v3 = acc[mt][nt][3] + bv1;
            if (RELU) {
                v0 = fmaxf(v0, 0.0f); v1 = fmaxf(v1, 0.0f);
                v2 = fmaxf(v2, 0.0f); v3 = fmaxf(v3, 0.0f);
            }
            store2(C, m0 * Nn + n0, v0, v1);
            store2(C, (m0 + 8) * Nn + n0, v2, v3);
        }
    }
}

// fp32 -> fp16, one-shot: each thread converts exactly 8 floats (2x float4).
// Grid must be sized so grid*256*8 == element count.
__global__ void conv_f16_oneshot(const float4* __restrict__ in,
                                 __half2* __restrict__ out)
{
    const int i = blockIdx.x * blockDim.x + threadIdx.x;
    float4 a = in[2 * i];
    float4 b = in[2 * i + 1];
    __half2 o[4];
    o[0] = __halves2half2(__float2half_rn(a.x), __float2half_rn(a.y));
    o[1] = __halves2half2(__float2half_rn(a.z), __float2half_rn(a.w));
    o[2] = __halves2half2(__float2half_rn(b.x), __float2half_rn(b.y));
    o[3] = __halves2half2(__float2half_rn(b.z), __float2half_rn(b.w));
    *reinterpret_cast<uint4*>(out + 4 * i) = *reinterpret_cast<uint4*>(o);
}

// bsum = b_ih + b_hh
__global__ void bias_sum_kernel(const float* __restrict__ a,
                                const float* __restrict__ b,
                                float* __restrict__ o, int n)
{
    int i = blockIdx.x * blockDim.x + threadIdx.x;
    if (i < n) o[i] = a[i] + b[i];
}

extern "C" void kernel_launch(void* const* d_in, const int* in_sizes, int n_in,
                              void* d_out, int out_size)
{
    const float* x       = (const float*)d_in[0];
    const float* W_init  = (const float*)d_in[1];
    const float* b_init  = (const float*)d_in[2];
    const float* W_ih    = (const float*)d_in[3];
    const float* b_ih    = (const float*)d_in[4];
    const float* b_hh    = (const float*)d_in[5];
    const float* W_final = (const float*)d_in[6];
    const float* b_final = (const float*)d_in[7];
    float* y = (float*)d_out;

    __half *xh, *hbuf, *mbuf, *w1, *w2, *w3;
    float* bsum;
    cudaGetSymbolAddress((void**)&xh,   g_xh);
    cudaGetSymbolAddress((void**)&hbuf, g_h);
    cudaGetSymbolAddress((void**)&mbuf, g_mid);
    cudaGetSymbolAddress((void**)&w1,   g_w1);
    cudaGetSymbolAddress((void**)&w2,   g_w2);
    cudaGetSymbolAddress((void**)&w3,   g_w3);
    cudaGetSymbolAddress((void**)&bsum, g_bsum);

    cudaFuncSetAttribute(gemm_f16<1024, true, __half>,
                         cudaFuncAttributeMaxDynamicSharedMemorySize, SMEM_TOTAL);
    cudaFuncSetAttribute(gemm_f16<2048, true, __half>,
                         cudaFuncAttributeMaxDynamicSharedMemorySize, SMEM_TOTAL);
    cudaFuncSetAttribute(gemm_f16<2048, false, float>,
                         cudaFuncAttributeMaxDynamicSharedMemorySize, SMEM_TOTAL);

    bias_sum_kernel<<<8, 256>>>(b_ih, b_hh, bsum, 2048);
    // one-shot conv: elements / (256 threads * 8 floats) blocks
    conv_f16_oneshot<<<(int)(M_TOK * 1024 / 2048), 256>>>((const float4*)x,       (__half2*)xh);  // 16384
    conv_f16_oneshot<<<2048 * 1024 / 2048, 256>>>((const float4*)W_init,  (__half2*)w1);          // 1024
    conv_f16_oneshot<<<2048 * 2048 / 2048, 256>>>((const float4*)W_ih,    (__half2*)w2);          // 2048
    conv_f16_oneshot<<<1024 * 2048 / 2048, 256>>>((const float4*)W_final, (__half2*)w3);          // 1024

    const dim3 block(NTHREADS, 1, 1);
    const dim3 grid12(2048 / BN, M_TOK / BM, 1);   // 16 x 256
    const dim3 grid3 (1024 / BN, M_TOK / BM, 1);   //  8 x 256

    gemm_f16<1024, true, __half><<<grid12, block, SMEM_TOTAL>>>(
        xh, w1, b_init, hbuf, 2048);
    gemm_f16<2048, true, __half><<<grid12, block, SMEM_TOTAL>>>(
        hbuf, w2, bsum, mbuf, 2048);
    gemm_f16<2048, false, float><<<grid3, block, SMEM_TOTAL>>>(
        mbuf, w3, b_final, y, 1024);
}

// round 13
// speedup vs baseline: 1.5375x; 1.5375x over previous
#include <cuda_runtime.h>
#include <cuda_fp16.h>
#include <cstdint>
#include <cstddef>

// ---------------------------------------------------------------------------
// RNNQNetworkZeroState, sm_103. fp16 m16n8k16 mma.sync, fp32 accumulate.
//   conv:  x,W1,W2,W3 fp32 -> fp16 (rn);  bsum = b_ih + b_hh
//   GEMM1: xh[M,1024]  @ W1h^T + b_init -> relu -> g_h   (half)
//   GEMM2: g_h[M,2048] @ W2h^T + bsum   -> relu -> g_mid (half)
//   GEMM3: g_mid       @ W3h^T + b_final -> out (float)
// Tile 128x128 (8 warps, 64x32 warp tiles, 2 CTAs/SM), BK=64 halves,
// 3-stage cp.async pipeline with the R4-proven ordering
// (PRODUCE i+2 -> wait_group 2 -> sync -> compute -> sync), B-fragment
// double buffering, K templated, grid-stride conv pre-passes.
// EXACT REVERT TO R10 (best: 1262 us) — R11's one-shot conv launch change
// coincided with a 680 us regression that its own 8 us profile cannot
// explain; this run disambiguates machine-state noise from a real effect.
// ---------------------------------------------------------------------------

#define BM 128
#define BN 128
#define BKH 64                 // halves per k-chunk = 128 bytes/row
#define NSTAGE 3
#define A_STAGE 16384          // 128 rows x 128 B
#define B_STAGE 16384
#define STAGE_BYTES (A_STAGE + B_STAGE)
#define SMEM_TOTAL (NSTAGE * STAGE_BYTES)   // 98304 B
#define NTHREADS 256

static constexpr size_t M_TOK = 32768;

// Scratch (allocation-free rule: __device__ globals).
__device__ __align__(16) __half g_xh  [M_TOK * 1024];
__device__ __align__(16) __half g_h   [M_TOK * 2048];
__device__ __align__(16) __half g_mid [M_TOK * 2048];
__device__ __align__(16) __half g_w1  [2048 * 1024];
__device__ __align__(16) __half g_w2  [2048 * 2048];
__device__ __align__(16) __half g_w3  [1024 * 2048];
__device__ __align__(16) float  g_bsum[2048];

#define SWZ(o) ((o) ^ (((o) >> 3) & 0x70))

__device__ __forceinline__ uint32_t s2u(const void* p) {
    uint32_t a;
    asm("{ .reg .u64 t; cvta.to.shared.u64 t, %1; cvt.u32.u64 %0, t; }"
        : "=r"(a) : "l"(p));
    return a;
}
__device__ __forceinline__ void cp16(uint32_t s, const void* g) {
    asm volatile("cp.async.cg.shared.global [%0], [%1], 16;" :: "r"(s), "l"(g));
}
__device__ __forceinline__ void ldsm4(uint32_t (&r)[4], uint32_t addr) {
    asm volatile("ldmatrix.sync.aligned.m8n8.x4.shared.b16 {%0,%1,%2,%3}, [%4];"
                 : "=r"(r[0]), "=r"(r[1]), "=r"(r[2]), "=r"(r[3]) : "r"(addr));
}
__device__ __forceinline__ void mma_f16(float (&d)[4], const uint32_t (&a)[4],
                                        uint32_t b0, uint32_t b1) {
    asm volatile(
        "mma.sync.aligned.m16n8k16.row.col.f32.f16.f16.f32 "
        "{%0,%1,%2,%3}, {%4,%5,%6,%7}, {%8,%9}, {%0,%1,%2,%3};"
        : "+f"(d[0]), "+f"(d[1]), "+f"(d[2]), "+f"(d[3])
        : "r"(a[0]), "r"(a[1]), "r"(a[2]), "r"(a[3]), "r"(b0), "r"(b1));
}

__device__ __forceinline__ void store2(__half* C, long off, float v0, float v1) {
    *reinterpret_cast<__half2*>(C + off) =
        __halves2half2(__float2half_rn(v0), __float2half_rn(v1));
}
__device__ __forceinline__ void store2(float* C, long off, float v0, float v1) {
    *reinterpret_cast<float2*>(C + off) = make_float2(v0, v1);
}

template <int K, bool RELU, typename TOUT>
__global__ void __launch_bounds__(NTHREADS, 2)
gemm_f16(const __half* __restrict__ A,     // [M,K] row-major
         const __half* __restrict__ W,     // [N,K] row-major
         const float* __restrict__ bias,   // [N]
         TOUT* __restrict__ C,             // [M,N]
         int Nn)
{
    extern __shared__ char smem[];
    const uint32_t sb = s2u(smem);

    const int tid  = threadIdx.x;
    const int lane = tid & 31;
    const int wid  = tid >> 5;
    const int wr   = wid >> 2;   // 0..1 : 64-row slab
    const int wc   = wid & 3;    // 0..3 : 32-col slab

    const long bm = (long)blockIdx.y * BM;
    const long bn = (long)blockIdx.x * BN;
    constexpr int nchunk = K / BKH;

    // ---- global->shared mapping: 8 threads/row (16B each), 4 rows/thread ----
    const int lrow = tid >> 3;         // 0..31
    const int lc16 = (tid & 7) * 16;   // byte col in 128B row
    const __half* Abase = A + (bm + lrow) * (long)K + (tid & 7) * 8;
    const __half* Bbase = W + (bn + lrow) * (long)K + (tid & 7) * 8;
    constexpr long rstep = 32L * K;    // 32-row advance (halves)

    uint32_t stoff[4];
    #pragma unroll
    for (int k = 0; k < 4; k++)
        stoff[k] = SWZ((uint32_t)((lrow + 32 * k) * 128 + lc16));

    // ---- ldmatrix address components ----
    const uint32_t xorv = (uint32_t)(lane & 7) << 4;           // swizzle xor
    uint32_t arow[4], brow[2];
    #pragma unroll
    for (int mt = 0; mt < 4; mt++)
        arow[mt] = (uint32_t)((wr * 64 + mt * 16 + (lane & 15)) * 128);
    #pragma unroll
    for (int p = 0; p < 2; p++)
        brow[p] = (uint32_t)((wc * 32 + p * 16 + (lane & 7) + ((lane >> 4) & 1) * 8) * 128);
    const uint32_t kA16 = ((lane >> 4) & 1) * 16;   // A: k+8 for lanes 16-31
    const uint32_t kB16 = ((lane >> 3) & 1) * 16;   // B: k+8 for lanes 8-15,24-31

    // per-ks k-byte offsets (post-swizzle xor folded in)
    uint32_t kbA[4], kbB[4];
    #pragma unroll
    for (int ks = 0; ks < 4; ks++) {
        kbA[ks] = ((uint32_t)(ks * 32) + kA16) ^ xorv;
        kbB[ks] = ((uint32_t)(ks * 32) + kB16) ^ xorv;
    }

    float acc[4][4][4];
    #pragma unroll
    for (int mt = 0; mt < 4; mt++)
        #pragma unroll
        for (int nt = 0; nt < 4; nt++)
            #pragma unroll
            for (int r = 0; r < 4; r++) acc[mt][nt][r] = 0.0f;

    #define PRODUCE(slot, kc)                                                   \
        do {                                                                    \
            const uint32_t _as = sb + (slot) * STAGE_BYTES;                     \
            const uint32_t _bs = _as + A_STAGE;                                 \
            const __half* _ap = Abase + (long)(kc) * BKH;                       \
            const __half* _bp = Bbase + (long)(kc) * BKH;                       \
            _Pragma("unroll")                                                   \
            for (int k = 0; k < 4; k++) {                                       \
                cp16(_as + stoff[k], _ap + k * rstep);                          \
                cp16(_bs + stoff[k], _bp + k * rstep);                          \
            }                                                                   \
            asm volatile("cp.async.commit_group;");                             \
        } while (0)

    // prologue: chunks 0,1 into slots 0,1
    PRODUCE(0, 0);
    PRODUCE(1, 1);

    int slot = 0, pslot = 2;
    #pragma unroll 3
    for (int i = 0; i < nchunk; i++) {
        if (i + 2 < nchunk) {
            PRODUCE(pslot, i + 2);
            asm volatile("cp.async.wait_group 2;");
        } else if (i + 1 < nchunk) {
            asm volatile("cp.async.wait_group 1;");
        } else {
            asm volatile("cp.async.wait_group 0;");
        }
        __syncthreads();

        const uint32_t stA = sb + slot * STAGE_BYTES;
        const uint32_t stB = stA + A_STAGE;

        // B-fragment double buffer: prefetch ks+1's B during ks's HMMA block.
        uint32_t bf[2][2][4];
        ldsm4(bf[0][0], stB + brow[0] + kbB[0]);
        ldsm4(bf[0][1], stB + brow[1] + kbB[0]);

        #pragma unroll
        for (int ks = 0; ks < 4; ks++) {
            const int cur = ks & 1;
            const int nxt = cur ^ 1;
            uint32_t af[4][4];
            #pragma unroll
            for (int mt = 0; mt < 4; mt++)
                ldsm4(af[mt], stA + arow[mt] + kbA[ks]);
            if (ks < 3) {
                ldsm4(bf[nxt][0], stB + brow[0] + kbB[ks + 1]);
                ldsm4(bf[nxt][1], stB + brow[1] + kbB[ks + 1]);
            }
            #pragma unroll
            for (int mt = 0; mt < 4; mt++)
                #pragma unroll
                for (int nt = 0; nt < 4; nt++)
                    mma_f16(acc[mt][nt], af[mt],
                            bf[cur][nt >> 1][(nt & 1) * 2],
                            bf[cur][nt >> 1][(nt & 1) * 2 + 1]);
        }
        __syncthreads();
        slot  = (slot  == NSTAGE - 1) ? 0 : slot + 1;
        pslot = (pslot == NSTAGE - 1) ? 0 : pslot + 1;
    }
    #undef PRODUCE

    // ---- epilogue ----
    const int gid = lane >> 2;     // row in 8-row group
    const int tin = lane & 3;      // column pair
    #pragma unroll
    for (int nt = 0; nt < 4; nt++) {
        const long n0 = bn + wc * 32 + nt * 8 + tin * 2;
        const float bv0 = bias[n0];
        const float bv1 = bias[n0 + 1];
        #pragma unroll
        for (int mt = 0; mt < 4; mt++) {
            const long m0 = bm + wr * 64 + mt * 16 + gid;
            float v0 = acc[mt][nt][0] + bv0;
            float v1 = acc[mt][nt][1] + bv1;
            float v2 = acc[mt][nt][2] + bv0;
            float v3 = acc[mt][nt][3] + bv1;
            if (RELU) {
                v0 = fmaxf(v0, 0.0f); v1 = fmaxf(v1, 0.0f);
                v2 = fmaxf(v2, 0.0f); v3 = fmaxf(v3, 0.0f);
            }
            store2(C, m0 * Nn + n0, v0, v1);
            store2(C, (m0 + 8) * Nn + n0, v2, v3);
        }
    }
}

// fp32 -> fp16 conversion, 16 floats/thread/iter, 2 independent streams (MLP).
__global__ void conv_f16_kernel(const float4* __restrict__ in,
                                __half2* __restrict__ out, int n16)
{
    int i = blockIdx.x * blockDim.x + threadIdx.x;
    const int stride = gridDim.x * blockDim.x;
    for (; i < n16; i += stride) {
        float4 a0 = in[4 * i];
        float4 a1 = in[4 * i + 1];
        float4 a2 = in[4 * i + 2];
        float4 a3 = in[4 * i + 3];
        __half2 o0[4], o1[4];
        o0[0] = __halves2half2(__float2half_rn(a0.x), __float2half_rn(a0.y));
        o0[1] = __halves2half2(__float2half_rn(a0.z), __float2half_rn(a0.w));
        o0[2] = __halves2half2(__float2half_rn(a1.x), __float2half_rn(a1.y));
        o0[3] = __halves2half2(__float2half_rn(a1.z), __float2half_rn(a1.w));
        o1[0] = __halves2half2(__float2half_rn(a2.x), __float2half_rn(a2.y));
        o1[1] = __halves2half2(__float2half_rn(a2.z), __float2half_rn(a2.w));
        o1[2] = __halves2half2(__float2half_rn(a3.x), __float2half_rn(a3.y));
        o1[3] = __halves2half2(__float2half_rn(a3.z), __float2half_rn(a3.w));
        *reinterpret_cast<uint4*>(out + 8 * i)     = *reinterpret_cast<uint4*>(o0);
        *reinterpret_cast<uint4*>(out + 8 * i + 4) = *reinterpret_cast<uint4*>(o1);
    }
}

// bsum = b_ih + b_hh
__global__ void bias_sum_kernel(const float* __restrict__ a,
                                const float* __restrict__ b,
                                float* __restrict__ o, int n)
{
    int i = blockIdx.x * blockDim.x + threadIdx.x;
    if (i < n) o[i] = a[i] + b[i];
}

extern "C" void kernel_launch(void* const* d_in, const int* in_sizes, int n_in,
                              void* d_out, int out_size)
{
    const float* x       = (const float*)d_in[0];
    const float* W_init  = (const float*)d_in[1];
    const float* b_init  = (const float*)d_in[2];
    const float* W_ih    = (const float*)d_in[3];
    const float* b_ih    = (const float*)d_in[4];
    const float* b_hh    = (const float*)d_in[5];
    const float* W_final = (const float*)d_in[6];
    const float* b_final = (const float*)d_in[7];
    float* y = (float*)d_out;

    __half *xh, *hbuf, *mbuf, *w1, *w2, *w3;
    float* bsum;
    cudaGetSymbolAddress((void**)&xh,   g_xh);
    cudaGetSymbolAddress((void**)&hbuf, g_h);
    cudaGetSymbolAddress((void**)&mbuf, g_mid);
    cudaGetSymbolAddress((void**)&w1,   g_w1);
    cudaGetSymbolAddress((void**)&w2,   g_w2);
    cudaGetSymbolAddress((void**)&w3,   g_w3);
    cudaGetSymbolAddress((void**)&bsum, g_bsum);

    cudaFuncSetAttribute(gemm_f16<1024, true, __half>,
                         cudaFuncAttributeMaxDynamicSharedMemorySize, SMEM_TOTAL);
    cudaFuncSetAttribute(gemm_f16<2048, true, __half>,
                         cudaFuncAttributeMaxDynamicSharedMemorySize, SMEM_TOTAL);
    cudaFuncSetAttribute(gemm_f16<2048, false, float>,
                         cudaFuncAttributeMaxDynamicSharedMemorySize, SMEM_TOTAL);

    bias_sum_kernel<<<8, 256>>>(b_ih, b_hh, bsum, 2048);
    conv_f16_kernel<<<2048, 256>>>((const float4*)x,       (__half2*)xh, (int)(M_TOK * 1024 / 16));
    conv_f16_kernel<<<512,  256>>>((const float4*)W_init,  (__half2*)w1, 2048 * 1024 / 16);
    conv_f16_kernel<<<512,  256>>>((const float4*)W_ih,    (__half2*)w2, 2048 * 2048 / 16);
    conv_f16_kernel<<<512,  256>>>((const float4*)W_final, (__half2*)w3, 1024 * 2048 / 16);

    const dim3 block(NTHREADS, 1, 1);
    const dim3 grid12(2048 / BN, M_TOK / BM, 1);   // 16 x 256
    const dim3 grid3 (1024 / BN, M_TOK / BM, 1);   //  8 x 256

    gemm_f16<1024, true, __half><<<grid12, block, SMEM_TOTAL>>>(
        xh, w1, b_init, hbuf, 2048);
    gemm_f16<2048, true, __half><<<grid12, block, SMEM_TOTAL>>>(
        hbuf, w2, bsum, mbuf, 2048);
    gemm_f16<2048, false, float><<<grid3, block, SMEM_TOTAL>>>(
        mbuf, w3, b_final, y, 1024);
}

// round 14
// speedup vs baseline: 1.5493x; 1.0077x over previous
#include <cuda_runtime.h>
#include <cuda_fp16.h>
#include <cstdint>
#include <cstddef>

// ---------------------------------------------------------------------------
// RNNQNetworkZeroState, sm_103. fp16 m16n8k16 mma.sync, fp32 accumulate.
//   prep:  ONE fused kernel: {x,W1,W2,W3} fp32->fp16 (rn) + bsum=b_ih+b_hh
//   GEMM1: xh[M,1024]  @ W1h^T + b_init -> relu -> g_h   (half)
//   GEMM2: g_h[M,2048] @ W2h^T + bsum   -> relu -> g_mid (half)
//   GEMM3: g_mid       @ W3h^T + b_final -> out (float)
// GEMM: tile 128x128 (8 warps, 64x32 warp tiles, 2 CTAs/SM), BK=64 halves,
// 3-stage cp.async pipeline, R4 ordering (PRODUCE i+2 -> wait_group 2 ->
// sync -> compute -> sync), B-fragment double buffering, K templated.
// GEMM path byte-identical to R10/R13 (1262 us, twice reproduced).
// ---------------------------------------------------------------------------

#define BM 128
#define BN 128
#define BKH 64                 // halves per k-chunk = 128 bytes/row
#define NSTAGE 3
#define A_STAGE 16384          // 128 rows x 128 B
#define B_STAGE 16384
#define STAGE_BYTES (A_STAGE + B_STAGE)
#define SMEM_TOTAL (NSTAGE * STAGE_BYTES)   // 98304 B
#define NTHREADS 256

static constexpr size_t M_TOK = 32768;

// Scratch (allocation-free rule: __device__ globals).
__device__ __align__(16) __half g_xh  [M_TOK * 1024];
__device__ __align__(16) __half g_h   [M_TOK * 2048];
__device__ __align__(16) __half g_mid [M_TOK * 2048];
__device__ __align__(16) __half g_w1  [2048 * 1024];
__device__ __align__(16) __half g_w2  [2048 * 2048];
__device__ __align__(16) __half g_w3  [1024 * 2048];
__device__ __align__(16) float  g_bsum[2048];

#define SWZ(o) ((o) ^ (((o) >> 3) & 0x70))

__device__ __forceinline__ uint32_t s2u(const void* p) {
    uint32_t a;
    asm("{ .reg .u64 t; cvta.to.shared.u64 t, %1; cvt.u32.u64 %0, t; }"
        : "=r"(a) : "l"(p));
    return a;
}
__device__ __forceinline__ void cp16(uint32_t s, const void* g) {
    asm volatile("cp.async.cg.shared.global [%0], [%1], 16;" :: "r"(s), "l"(g));
}
__device__ __forceinline__ void ldsm4(uint32_t (&r)[4], uint32_t addr) {
    asm volatile("ldmatrix.sync.aligned.m8n8.x4.shared.b16 {%0,%1,%2,%3}, [%4];"
                 : "=r"(r[0]), "=r"(r[1]), "=r"(r[2]), "=r"(r[3]) : "r"(addr));
}
__device__ __forceinline__ void mma_f16(float (&d)[4], const uint32_t (&a)[4],
                                        uint32_t b0, uint32_t b1) {
    asm volatile(
        "mma.sync.aligned.m16n8k16.row.col.f32.f16.f16.f32 "
        "{%0,%1,%2,%3}, {%4,%5,%6,%7}, {%8,%9}, {%0,%1,%2,%3};"
        : "+f"(d[0]), "+f"(d[1]), "+f"(d[2]), "+f"(d[3])
        : "r"(a[0]), "r"(a[1]), "r"(a[2]), "r"(a[3]), "r"(b0), "r"(b1));
}

__device__ __forceinline__ void store2(__half* C, long off, float v0, float v1) {
    *reinterpret_cast<__half2*>(C + off) =
        __halves2half2(__float2half_rn(v0), __float2half_rn(v1));
}
__device__ __forceinline__ void store2(float* C, long off, float v0, float v1) {
    *reinterpret_cast<float2*>(C + off) = make_float2(v0, v1);
}

template <int K, bool RELU, typename TOUT>
__global__ void __launch_bounds__(NTHREADS, 2)
gemm_f16(const __half* __restrict__ A,     // [M,K] row-major
         const __half* __restrict__ W,     // [N,K] row-major
         const float* __restrict__ bias,   // [N]
         TOUT* __restrict__ C,             // [M,N]
         int Nn)
{
    extern __shared__ char smem[];
    const uint32_t sb = s2u(smem);

    const int tid  = threadIdx.x;
    const int lane = tid & 31;
    const int wid  = tid >> 5;
    const int wr   = wid >> 2;   // 0..1 : 64-row slab
    const int wc   = wid & 3;    // 0..3 : 32-col slab

    const long bm = (long)blockIdx.y * BM;
    const long bn = (long)blockIdx.x * BN;
    constexpr int nchunk = K / BKH;

    // ---- global->shared mapping: 8 threads/row (16B each), 4 rows/thread ----
    const int lrow = tid >> 3;         // 0..31
    const int lc16 = (tid & 7) * 16;   // byte col in 128B row
    const __half* Abase = A + (bm + lrow) * (long)K + (tid & 7) * 8;
    const __half* Bbase = W + (bn + lrow) * (long)K + (tid & 7) * 8;
    constexpr long rstep = 32L * K;    // 32-row advance (halves)

    uint32_t stoff[4];
    #pragma unroll
    for (int k = 0; k < 4; k++)
        stoff[k] = SWZ((uint32_t)((lrow + 32 * k) * 128 + lc16));

    // ---- ldmatrix address components ----
    const uint32_t xorv = (uint32_t)(lane & 7) << 4;           // swizzle xor
    uint32_t arow[4], brow[2];
    #pragma unroll
    for (int mt = 0; mt < 4; mt++)
        arow[mt] = (uint32_t)((wr * 64 + mt * 16 + (lane & 15)) * 128);
    #pragma unroll
    for (int p = 0; p < 2; p++)
        brow[p] = (uint32_t)((wc * 32 + p * 16 + (lane & 7) + ((lane >> 4) & 1) * 8) * 128);
    const uint32_t kA16 = ((lane >> 4) & 1) * 16;   // A: k+8 for lanes 16-31
    const uint32_t kB16 = ((lane >> 3) & 1) * 16;   // B: k+8 for lanes 8-15,24-31

    // per-ks k-byte offsets (post-swizzle xor folded in)
    uint32_t kbA[4], kbB[4];
    #pragma unroll
    for (int ks = 0; ks < 4; ks++) {
        kbA[ks] = ((uint32_t)(ks * 32) + kA16) ^ xorv;
        kbB[ks] = ((uint32_t)(ks * 32) + kB16) ^ xorv;
    }

    float acc[4][4][4];
    #pragma unroll
    for (int mt = 0; mt < 4; mt++)
        #pragma unroll
        for (int nt = 0; nt < 4; nt++)
            #pragma unroll
            for (int r = 0; r < 4; r++) acc[mt][nt][r] = 0.0f;

    #define PRODUCE(slot, kc)                                                   \
        do {                                                                    \
            const uint32_t _as = sb + (slot) * STAGE_BYTES;                     \
            const uint32_t _bs = _as + A_STAGE;                                 \
            const __half* _ap = Abase + (long)(kc) * BKH;                       \
            const __half* _bp = Bbase + (long)(kc) * BKH;                       \
            _Pragma("unroll")                                                   \
            for (int k = 0; k < 4; k++) {                                       \
                cp16(_as + stoff[k], _ap + k * rstep);                          \
                cp16(_bs + stoff[k], _bp + k * rstep);                          \
            }                                                                   \
            asm volatile("cp.async.commit_group;");                             \
        } while (0)

    // prologue: chunks 0,1 into slots 0,1
    PRODUCE(0, 0);
    PRODUCE(1, 1);

    int slot = 0, pslot = 2;
    #pragma unroll 3
    for (int i = 0; i < nchunk; i++) {
        if (i + 2 < nchunk) {
            PRODUCE(pslot, i + 2);
            asm volatile("cp.async.wait_group 2;");
        } else if (i + 1 < nchunk) {
            asm volatile("cp.async.wait_group 1;");
        } else {
            asm volatile("cp.async.wait_group 0;");
        }
        __syncthreads();

        const uint32_t stA = sb + slot * STAGE_BYTES;
        const uint32_t stB = stA + A_STAGE;

        // B-fragment double buffer: prefetch ks+1's B during ks's HMMA block.
        uint32_t bf[2][2][4];
        ldsm4(bf[0][0], stB + brow[0] + kbB[0]);
        ldsm4(bf[0][1], stB + brow[1] + kbB[0]);

        #pragma unroll
        for (int ks = 0; ks < 4; ks++) {
            const int cur = ks & 1;
            const int nxt = cur ^ 1;
            uint32_t af[4][4];
            #pragma unroll
            for (int mt = 0; mt < 4; mt++)
                ldsm4(af[mt], stA + arow[mt] + kbA[ks]);
            if (ks < 3) {
                ldsm4(bf[nxt][0], stB + brow[0] + kbB[ks + 1]);
                ldsm4(bf[nxt][1], stB + brow[1] + kbB[ks + 1]);
            }
            #pragma unroll
            for (int mt = 0; mt < 4; mt++)
                #pragma unroll
                for (int nt = 0; nt < 4; nt++)
                    mma_f16(acc[mt][nt], af[mt],
                            bf[cur][nt >> 1][(nt & 1) * 2],
                            bf[cur][nt >> 1][(nt & 1) * 2 + 1]);
        }
        __syncthreads();
        slot  = (slot  == NSTAGE - 1) ? 0 : slot + 1;
        pslot = (pslot == NSTAGE - 1) ? 0 : pslot + 1;
    }
    #undef PRODUCE

    // ---- epilogue ----
    const int gid = lane >> 2;     // row in 8-row group
    const int tin = lane & 3;      // column pair
    #pragma unroll
    for (int nt = 0; nt < 4; nt++) {
        const long n0 = bn + wc * 32 + nt * 8 + tin * 2;
        const float bv0 = bias[n0];
        const float bv1 = bias[n0 + 1];
        #pragma unroll
        for (int mt = 0; mt < 4; mt++) {
            const long m0 = bm + wr * 64 + mt * 16 + gid;
            float v0 = acc[mt][nt][0] + bv0;
            float v1 = acc[mt][nt][1] + bv1;
            float v2 = acc[mt][nt][2] + bv0;
            float v3 = acc[mt][nt][3] + bv1;
            if (RELU) {
                v0 = fmaxf(v0, 0.0f); v1 = fmaxf(v1, 0.0f);
                v2 = fmaxf(v2, 0.0f); v3 = fmaxf(v3, 0.0f);
            }
            store2(C, m0 * Nn + n0, v0, v1);
            store2(C, (m0 + 8) * Nn + n0, v2, v3);
        }
    }
}

// ---- fused prep: convert 4 tensors fp32->fp16 + bias sum, one launch ----
// Segment sizes in 16-float units.
#define NX  ((int)(M_TOK * 1024 / 16))      // 2097152
#define NW1 (2048 * 1024 / 16)              // 131072
#define NW2 (2048 * 2048 / 16)              // 262144
#define NW3 (1024 * 2048 / 16)              // 131072
#define NTOT (NX + NW1 + NW2 + NW3)         // 2621440

__device__ __forceinline__ void conv16(const float4* __restrict__ in,
                                       __half2* __restrict__ out, int i)
{
    float4 a0 = in[4 * i];
    float4 a1 = in[4 * i + 1];
    float4 a2 = in[4 * i + 2];
    float4 a3 = in[4 * i + 3];
    __half2 o0[4], o1[4];
    o0[0] = __halves2half2(__float2half_rn(a0.x), __float2half_rn(a0.y));
    o0[1] = __halves2half2(__float2half_rn(a0.z), __float2half_rn(a0.w));
    o0[2] = __halves2half2(__float2half_rn(a1.x), __float2half_rn(a1.y));
    o0[3] = __halves2half2(__float2half_rn(a1.z), __float2half_rn(a1.w));
    o1[0] = __halves2half2(__float2half_rn(a2.x), __float2half_rn(a2.y));
    o1[1] = __halves2half2(__float2half_rn(a2.z), __float2half_rn(a2.w));
    o1[2] = __halves2half2(__float2half_rn(a3.x), __float2half_rn(a3.y));
    o1[3] = __halves2half2(__float2half_rn(a3.z), __float2half_rn(a3.w));
    *reinterpret_cast<uint4*>(out + 8 * i)     = *reinterpret_cast<uint4*>(o0);
    *reinterpret_cast<uint4*>(out + 8 * i + 4) = *reinterpret_cast<uint4*>(o1);
}

__global__ void prep_kernel(const float4* __restrict__ x,   __half2* __restrict__ xh,
                            const float4* __restrict__ w1f, __half2* __restrict__ w1h,
                            const float4* __restrict__ w2f, __half2* __restrict__ w2h,
                            const float4* __restrict__ w3f, __half2* __restrict__ w3h,
                            const float* __restrict__ bih,  const float* __restrict__ bhh,
                            float* __restrict__ bsum)
{
    const int gtid = blockIdx.x * blockDim.x + threadIdx.x;
    if (gtid < 2048) bsum[gtid] = bih[gtid] + bhh[gtid];

    const int stride = gridDim.x * blockDim.x;
    for (int i = gtid; i < NTOT; i += stride) {
        if (i < NX) {
            conv16(x, xh, i);
        } else if (i < NX + NW1) {
            conv16(w1f, w1h, i - NX);
        } else if (i < NX + NW1 + NW2) {
            conv16(w2f, w2h, i - NX - NW1);
        } else {
            conv16(w3f, w3h, i - NX - NW1 - NW2);
        }
    }
}

extern "C" void kernel_launch(void* const* d_in, const int* in_sizes, int n_in,
                              void* d_out, int out_size)
{
    const float* x       = (const float*)d_in[0];
    const float* W_init  = (const float*)d_in[1];
    const float* b_init  = (const float*)d_in[2];
    const float* W_ih    = (const float*)d_in[3];
    const float* b_ih    = (const float*)d_in[4];
    const float* b_hh    = (const float*)d_in[5];
    const float* W_final = (const float*)d_in[6];
    const float* b_final = (const float*)d_in[7];
    float* y = (float*)d_out;

    __half *xh, *hbuf, *mbuf, *w1, *w2, *w3;
    float* bsum;
    cudaGetSymbolAddress((void**)&xh,   g_xh);
    cudaGetSymbolAddress((void**)&hbuf, g_h);
    cudaGetSymbolAddress((void**)&mbuf, g_mid);
    cudaGetSymbolAddress((void**)&w1,   g_w1);
    cudaGetSymbolAddress((void**)&w2,   g_w2);
    cudaGetSymbolAddress((void**)&w3,   g_w3);
    cudaGetSymbolAddress((void**)&bsum, g_bsum);

    cudaFuncSetAttribute(gemm_f16<1024, true, __half>,
                         cudaFuncAttributeMaxDynamicSharedMemorySize, SMEM_TOTAL);
    cudaFuncSetAttribute(gemm_f16<2048, true, __half>,
                         cudaFuncAttributeMaxDynamicSharedMemorySize, SMEM_TOTAL);
    cudaFuncSetAttribute(gemm_f16<2048, false, float>,
                         cudaFuncAttributeMaxDynamicSharedMemorySize, SMEM_TOTAL);

    // one fused prep launch (same 2048x256 geometry as the proven x-conv)
    prep_kernel<<<2048, 256>>>((const float4*)x,       (__half2*)xh,
                               (const float4*)W_init,  (__half2*)w1,
                               (const float4*)W_ih,    (__half2*)w2,
                               (const float4*)W_final, (__half2*)w3,
                               b_ih, b_hh, bsum);

    const dim3 block(NTHREADS, 1, 1);
    const dim3 grid12(2048 / BN, M_TOK / BM, 1);   // 16 x 256
    const dim3 grid3 (1024 / BN, M_TOK / BM, 1);   //  8 x 256

    gemm_f16<1024, true, __half><<<grid12, block, SMEM_TOTAL>>>(
        xh, w1, b_init, hbuf, 2048);
    gemm_f16<2048, true, __half><<<grid12, block, SMEM_TOTAL>>>(
        hbuf, w2, bsum, mbuf, 2048);
    gemm_f16<2048, false, float><<<grid3, block, SMEM_TOTAL>>>(
        mbuf, w3, b_final, y, 1024);
}

// round 15
// speedup vs baseline: 1.5548x; 1.0035x over previous
#include <cuda_runtime.h>
#include <cuda_fp16.h>
#include <cstdint>
#include <cstddef>

// ---------------------------------------------------------------------------
// RNNQNetworkZeroState, sm_103. fp16 m16n8k16 mma.sync, fp32 accumulate.
//   prep:  ONE fused kernel: {x,W1,W2,W3} fp32->fp16 (rn) + bsum=b_ih+b_hh
//   GEMM1: xh[M,1024]  @ W1h^T + b_init -> relu -> g_h   (half)
//   GEMM2: g_h[M,2048] @ W2h^T + bsum   -> relu -> g_mid (half)
//   GEMM3: g_mid       @ W3h^T + b_final -> out (float)
// GEMM: tile 128x128 (8 warps, 64x32 warp tiles, 2 CTAs/SM), BK=64 halves,
// 3-stage cp.async pipeline, R4 ordering, B-fragment double buffering,
// K templated. New this round: CTA bias slice cp.async'd into smem inside
// the chunk-0 commit group (wait_group FIFO untouched) -> epilogue reads
// bias via LDS instead of an all-warp ~600cyc LDG stall.
// ---------------------------------------------------------------------------

#define BM 128
#define BN 128
#define BKH 64                 // halves per k-chunk = 128 bytes/row
#define NSTAGE 3
#define A_STAGE 16384          // 128 rows x 128 B
#define B_STAGE 16384
#define STAGE_BYTES (A_STAGE + B_STAGE)
#define BIAS_SMEM (NSTAGE * STAGE_BYTES)    // 512B bias slice after stages
#define SMEM_TOTAL (BIAS_SMEM + 512)        // 98816 B
#define NTHREADS 256

static constexpr size_t M_TOK = 32768;

// Scratch (allocation-free rule: __device__ globals).
__device__ __align__(16) __half g_xh  [M_TOK * 1024];
__device__ __align__(16) __half g_h   [M_TOK * 2048];
__device__ __align__(16) __half g_mid [M_TOK * 2048];
__device__ __align__(16) __half g_w1  [2048 * 1024];
__device__ __align__(16) __half g_w2  [2048 * 2048];
__device__ __align__(16) __half g_w3  [1024 * 2048];
__device__ __align__(16) float  g_bsum[2048];

#define SWZ(o) ((o) ^ (((o) >> 3) & 0x70))

__device__ __forceinline__ uint32_t s2u(const void* p) {
    uint32_t a;
    asm("{ .reg .u64 t; cvta.to.shared.u64 t, %1; cvt.u32.u64 %0, t; }"
        : "=r"(a) : "l"(p));
    return a;
}
__device__ __forceinline__ void cp16(uint32_t s, const void* g) {
    asm volatile("cp.async.cg.shared.global [%0], [%1], 16;" :: "r"(s), "l"(g));
}
__device__ __forceinline__ void ldsm4(uint32_t (&r)[4], uint32_t addr) {
    asm volatile("ldmatrix.sync.aligned.m8n8.x4.shared.b16 {%0,%1,%2,%3}, [%4];"
                 : "=r"(r[0]), "=r"(r[1]), "=r"(r[2]), "=r"(r[3]) : "r"(addr));
}
__device__ __forceinline__ void mma_f16(float (&d)[4], const uint32_t (&a)[4],
                                        uint32_t b0, uint32_t b1) {
    asm volatile(
        "mma.sync.aligned.m16n8k16.row.col.f32.f16.f16.f32 "
        "{%0,%1,%2,%3}, {%4,%5,%6,%7}, {%8,%9}, {%0,%1,%2,%3};"
        : "+f"(d[0]), "+f"(d[1]), "+f"(d[2]), "+f"(d[3])
        : "r"(a[0]), "r"(a[1]), "r"(a[2]), "r"(a[3]), "r"(b0), "r"(b1));
}

__device__ __forceinline__ void store2(__half* C, long off, float v0, float v1) {
    *reinterpret_cast<__half2*>(C + off) =
        __halves2half2(__float2half_rn(v0), __float2half_rn(v1));
}
__device__ __forceinline__ void store2(float* C, long off, float v0, float v1) {
    *reinterpret_cast<float2*>(C + off) = make_float2(v0, v1);
}

template <int K, bool RELU, typename TOUT>
__global__ void __launch_bounds__(NTHREADS, 2)
gemm_f16(const __half* __restrict__ A,     // [M,K] row-major
         const __half* __restrict__ W,     // [N,K] row-major
         const float* __restrict__ bias,   // [N]
         TOUT* __restrict__ C,             // [M,N]
         int Nn)
{
    extern __shared__ char smem[];
    const uint32_t sb = s2u(smem);

    const int tid  = threadIdx.x;
    const int lane = tid & 31;
    const int wid  = tid >> 5;
    const int wr   = wid >> 2;   // 0..1 : 64-row slab
    const int wc   = wid & 3;    // 0..3 : 32-col slab

    const long bm = (long)blockIdx.y * BM;
    const long bn = (long)blockIdx.x * BN;
    constexpr int nchunk = K / BKH;

    // ---- global->shared mapping: 8 threads/row (16B each), 4 rows/thread ----
    const int lrow = tid >> 3;         // 0..31
    const int lc16 = (tid & 7) * 16;   // byte col in 128B row
    const __half* Abase = A + (bm + lrow) * (long)K + (tid & 7) * 8;
    const __half* Bbase = W + (bn + lrow) * (long)K + (tid & 7) * 8;
    constexpr long rstep = 32L * K;    // 32-row advance (halves)

    uint32_t stoff[4];
    #pragma unroll
    for (int k = 0; k < 4; k++)
        stoff[k] = SWZ((uint32_t)((lrow + 32 * k) * 128 + lc16));

    // ---- ldmatrix address components ----
    const uint32_t xorv = (uint32_t)(lane & 7) << 4;           // swizzle xor
    uint32_t arow[4], brow[2];
    #pragma unroll
    for (int mt = 0; mt < 4; mt++)
        arow[mt] = (uint32_t)((wr * 64 + mt * 16 + (lane & 15)) * 128);
    #pragma unroll
    for (int p = 0; p < 2; p++)
        brow[p] = (uint32_t)((wc * 32 + p * 16 + (lane & 7) + ((lane >> 4) & 1) * 8) * 128);
    const uint32_t kA16 = ((lane >> 4) & 1) * 16;   // A: k+8 for lanes 16-31
    const uint32_t kB16 = ((lane >> 3) & 1) * 16;   // B: k+8 for lanes 8-15,24-31

    // per-ks k-byte offsets (post-swizzle xor folded in)
    uint32_t kbA[4], kbB[4];
    #pragma unroll
    for (int ks = 0; ks < 4; ks++) {
        kbA[ks] = ((uint32_t)(ks * 32) + kA16) ^ xorv;
        kbB[ks] = ((uint32_t)(ks * 32) + kB16) ^ xorv;
    }

    float acc[4][4][4];
    #pragma unroll
    for (int mt = 0; mt < 4; mt++)
        #pragma unroll
        for (int nt = 0; nt < 4; nt++)
            #pragma unroll
            for (int r = 0; r < 4; r++) acc[mt][nt][r] = 0.0f;

    #define PRODUCE(slot, kc)                                                   \
        do {                                                                    \
            const uint32_t _as = sb + (slot) * STAGE_BYTES;                     \
            const uint32_t _bs = _as + A_STAGE;                                 \
            const __half* _ap = Abase + (long)(kc) * BKH;                       \
            const __half* _bp = Bbase + (long)(kc) * BKH;                       \
            _Pragma("unroll")                                                   \
            for (int k = 0; k < 4; k++) {                                       \
                cp16(_as + stoff[k], _ap + k * rstep);                          \
                cp16(_bs + stoff[k], _bp + k * rstep);                          \
            }                                                                   \
            asm volatile("cp.async.commit_group;");                             \
        } while (0)

    // prologue: chunk 0 (plus the CTA's 512B bias slice, same commit group
    // so all wait_group counts downstream are unchanged), then chunk 1.
    {
        const uint32_t _as = sb;
        const uint32_t _bs = sb + A_STAGE;
        #pragma unroll
        for (int k = 0; k < 4; k++) {
            cp16(_as + stoff[k], Abase + k * rstep);
            cp16(_bs + stoff[k], Bbase + k * rstep);
        }
        if (tid < 32) cp16(sb + BIAS_SMEM + tid * 16, bias + bn + tid * 4);
        asm volatile("cp.async.commit_group;");
    }
    PRODUCE(1, 1);

    int slot = 0, pslot = 2;
    #pragma unroll 3
    for (int i = 0; i < nchunk; i++) {
        if (i + 2 < nchunk) {
            PRODUCE(pslot, i + 2);
            asm volatile("cp.async.wait_group 2;");
        } else if (i + 1 < nchunk) {
            asm volatile("cp.async.wait_group 1;");
        } else {
            asm volatile("cp.async.wait_group 0;");
        }
        __syncthreads();

        const uint32_t stA = sb + slot * STAGE_BYTES;
        const uint32_t stB = stA + A_STAGE;

        // B-fragment double buffer: prefetch ks+1's B during ks's HMMA block.
        uint32_t bf[2][2][4];
        ldsm4(bf[0][0], stB + brow[0] + kbB[0]);
        ldsm4(bf[0][1], stB + brow[1] + kbB[0]);

        #pragma unroll
        for (int ks = 0; ks < 4; ks++) {
            const int cur = ks & 1;
            const int nxt = cur ^ 1;
            uint32_t af[4][4];
            #pragma unroll
            for (int mt = 0; mt < 4; mt++)
                ldsm4(af[mt], stA + arow[mt] + kbA[ks]);
            if (ks < 3) {
                ldsm4(bf[nxt][0], stB + brow[0] + kbB[ks + 1]);
                ldsm4(bf[nxt][1], stB + brow[1] + kbB[ks + 1]);
            }
            #pragma unroll
            for (int mt = 0; mt < 4; mt++)
                #pragma unroll
                for (int nt = 0; nt < 4; nt++)
                    mma_f16(acc[mt][nt], af[mt],
                            bf[cur][nt >> 1][(nt & 1) * 2],
                            bf[cur][nt >> 1][(nt & 1) * 2 + 1]);
        }
        __syncthreads();
        slot  = (slot  == NSTAGE - 1) ? 0 : slot + 1;
        pslot = (pslot == NSTAGE - 1) ? 0 : pslot + 1;
    }
    #undef PRODUCE

    // ---- epilogue: bias from smem (arrived with chunk-0 group) ----
    const float* bsm = reinterpret_cast<const float*>(smem + BIAS_SMEM);
    const int gid = lane >> 2;     // row in 8-row group
    const int tin = lane & 3;      // column pair
    #pragma unroll
    for (int nt = 0; nt < 4; nt++) {
        const int  nl = wc * 32 + nt * 8 + tin * 2;   // local col in [0,128)
        const long n0 = bn + nl;
        const float bv0 = bsm[nl];
        const float bv1 = bsm[nl + 1];
        #pragma unroll
        for (int mt = 0; mt < 4; mt++) {
            const long m0 = bm + wr * 64 + mt * 16 + gid;
            float v0 = acc[mt][nt][0] + bv0;
            float v1 = acc[mt][nt][1] + bv1;
            float v2 = acc[mt][nt][2] + bv0;
            float v3 = acc[mt][nt][3] + bv1;
            if (RELU) {
                v0 = fmaxf(v0, 0.0f); v1 = fmaxf(v1, 0.0f);
                v2 = fmaxf(v2, 0.0f); v3 = fmaxf(v3, 0.0f);
            }
            store2(C, m0 * Nn + n0, v0, v1);
            store2(C, (m0 + 8) * Nn + n0, v2, v3);
        }
    }
}

// ---- fused prep: convert 4 tensors fp32->fp16 + bias sum, one launch ----
#define NX  ((int)(M_TOK * 1024 / 16))      // 2097152
#define NW1 (2048 * 1024 / 16)              // 131072
#define NW2 (2048 * 2048 / 16)              // 262144
#define NW3 (1024 * 2048 / 16)              // 131072
#define NTOT (NX + NW1 + NW2 + NW3)         // 2621440

__device__ __forceinline__ void conv16(const float4* __restrict__ in,
                                       __half2* __restrict__ out, int i)
{
    float4 a0 = in[4 * i];
    float4 a1 = in[4 * i + 1];
    float4 a2 = in[4 * i + 2];
    float4 a3 = in[4 * i + 3];
    __half2 o0[4], o1[4];
    o0[0] = __halves2half2(__float2half_rn(a0.x), __float2half_rn(a0.y));
    o0[1] = __halves2half2(__float2half_rn(a0.z), __float2half_rn(a0.w));
    o0[2] = __halves2half2(__float2half_rn(a1.x), __float2half_rn(a1.y));
    o0[3] = __halves2half2(__float2half_rn(a1.z), __float2half_rn(a1.w));
    o1[0] = __halves2half2(__float2half_rn(a2.x), __float2half_rn(a2.y));
    o1[1] = __halves2half2(__float2half_rn(a2.z), __float2half_rn(a2.w));
    o1[2] = __halves2half2(__float2half_rn(a3.x), __float2half_rn(a3.y));
    o1[3] = __halves2half2(__float2half_rn(a3.z), __float2half_rn(a3.w));
    *reinterpret_cast<uint4*>(out + 8 * i)     = *reinterpret_cast<uint4*>(o0);
    *reinterpret_cast<uint4*>(out + 8 * i + 4) = *reinterpret_cast<uint4*>(o1);
}

__global__ void prep_kernel(const float4* __restrict__ x,   __half2* __restrict__ xh,
                            const float4* __restrict__ w1f, __half2* __restrict__ w1h,
                            const float4* __restrict__ w2f, __half2* __restrict__ w2h,
                            const float4* __restrict__ w3f, __half2* __restrict__ w3h,
                            const float* __restrict__ bih,  const float* __restrict__ bhh,
                            float* __restrict__ bsum)
{
    const int gtid = blockIdx.x * blockDim.x + threadIdx.x;
    if (gtid < 2048) bsum[gtid] = bih[gtid] + bhh[gtid];

    const int stride = gridDim.x * blockDim.x;
    for (int i = gtid; i < NTOT; i += stride) {
        if (i < NX) {
            conv16(x, xh, i);
        } else if (i < NX + NW1) {
            conv16(w1f, w1h, i - NX);
        } else if (i < NX + NW1 + NW2) {
            conv16(w2f, w2h, i - NX - NW1);
        } else {
            conv16(w3f, w3h, i - NX - NW1 - NW2);
        }
    }
}

extern "C" void kernel_launch(void* const* d_in, const int* in_sizes, int n_in,
                              void* d_out, int out_size)
{
    const float* x       = (const float*)d_in[0];
    const float* W_init  = (const float*)d_in[1];
    const float* b_init  = (const float*)d_in[2];
    const float* W_ih    = (const float*)d_in[3];
    const float* b_ih    = (const float*)d_in[4];
    const float* b_hh    = (const float*)d_in[5];
    const float* W_final = (const float*)d_in[6];
    const float* b_final = (const float*)d_in[7];
    float* y = (float*)d_out;

    __half *xh, *hbuf, *mbuf, *w1, *w2, *w3;
    float* bsum;
    cudaGetSymbolAddress((void**)&xh,   g_xh);
    cudaGetSymbolAddress((void**)&hbuf, g_h);
    cudaGetSymbolAddress((void**)&mbuf, g_mid);
    cudaGetSymbolAddress((void**)&w1,   g_w1);
    cudaGetSymbolAddress((void**)&w2,   g_w2);
    cudaGetSymbolAddress((void**)&w3,   g_w3);
    cudaGetSymbolAddress((void**)&bsum, g_bsum);

    cudaFuncSetAttribute(gemm_f16<1024, true, __half>,
                         cudaFuncAttributeMaxDynamicSharedMemorySize, SMEM_TOTAL);
    cudaFuncSetAttribute(gemm_f16<2048, true, __half>,
                         cudaFuncAttributeMaxDynamicSharedMemorySize, SMEM_TOTAL);
    cudaFuncSetAttribute(gemm_f16<2048, false, float>,
                         cudaFuncAttributeMaxDynamicSharedMemorySize, SMEM_TOTAL);

    // one fused prep launch (proven 2048x256 geometry)
    prep_kernel<<<2048, 256>>>((const float4*)x,       (__half2*)xh,
                               (const float4*)W_init,  (__half2*)w1,
                               (const float4*)W_ih,    (__half2*)w2,
                               (const float4*)W_final, (__half2*)w3,
                               b_ih, b_hh, bsum);

    const dim3 block(NTHREADS, 1, 1);
    const dim3 grid12(2048 / BN, M_TOK / BM, 1);   // 16 x 256
    const dim3 grid3 (1024 / BN, M_TOK / BM, 1);   //  8 x 256

    gemm_f16<1024, true, __half><<<grid12, block, SMEM_TOTAL>>>(
        xh, w1, b_init, hbuf, 2048);
    gemm_f16<2048, true, __half><<<grid12, block, SMEM_TOTAL>>>(
        hbuf, w2, bsum, mbuf, 2048);
    gemm_f16<2048, false, float><<<grid3, block, SMEM_TOTAL>>>(
        mbuf, w3, b_final, y, 1024);
}

// round 16
// speedup vs baseline: 1.5602x; 1.0035x over previous
#include <cuda_runtime.h>
#include <cuda_fp16.h>
#include <cstdint>
#include <cstddef>

// ---------------------------------------------------------------------------
// RNNQNetworkZeroState, sm_103. fp16 m16n8k16 mma.sync, fp32 accumulate.
//   prep:  ONE fused kernel: {x,W1,W2,W3} fp32->fp16 (rn) + bsum=b_ih+b_hh
//   GEMM1: xh[M,1024]  @ W1h^T + b_init -> relu -> g_h   (half)
//   GEMM2: g_h[M,2048] @ W2h^T + bsum   -> relu -> g_mid (half)
//   GEMM3: g_mid       @ W3h^T + b_final -> out (float)
// GEMM: tile 128x128 (8 warps, 64x32 warp tiles, 2 CTAs/SM), BK=64 halves,
// 3-stage cp.async pipeline, R4 ordering, B-fragment double buffering,
// K templated, bias staged to smem in the chunk-0 commit group.
// This round: prep grid 2048 -> 4096 (prep was latency-bound at 2.3TB/s;
// more resident threads -> closer to the ~6TB/s DRAM ceiling).
// ---------------------------------------------------------------------------

#define BM 128
#define BN 128
#define BKH 64                 // halves per k-chunk = 128 bytes/row
#define NSTAGE 3
#define A_STAGE 16384          // 128 rows x 128 B
#define B_STAGE 16384
#define STAGE_BYTES (A_STAGE + B_STAGE)
#define BIAS_SMEM (NSTAGE * STAGE_BYTES)    // 512B bias slice after stages
#define SMEM_TOTAL (BIAS_SMEM + 512)        // 98816 B
#define NTHREADS 256

static constexpr size_t M_TOK = 32768;

// Scratch (allocation-free rule: __device__ globals).
__device__ __align__(16) __half g_xh  [M_TOK * 1024];
__device__ __align__(16) __half g_h   [M_TOK * 2048];
__device__ __align__(16) __half g_mid [M_TOK * 2048];
__device__ __align__(16) __half g_w1  [2048 * 1024];
__device__ __align__(16) __half g_w2  [2048 * 2048];
__device__ __align__(16) __half g_w3  [1024 * 2048];
__device__ __align__(16) float  g_bsum[2048];

#define SWZ(o) ((o) ^ (((o) >> 3) & 0x70))

__device__ __forceinline__ uint32_t s2u(const void* p) {
    uint32_t a;
    asm("{ .reg .u64 t; cvta.to.shared.u64 t, %1; cvt.u32.u64 %0, t; }"
        : "=r"(a) : "l"(p));
    return a;
}
__device__ __forceinline__ void cp16(uint32_t s, const void* g) {
    asm volatile("cp.async.cg.shared.global [%0], [%1], 16;" :: "r"(s), "l"(g));
}
__device__ __forceinline__ void ldsm4(uint32_t (&r)[4], uint32_t addr) {
    asm volatile("ldmatrix.sync.aligned.m8n8.x4.shared.b16 {%0,%1,%2,%3}, [%4];"
                 : "=r"(r[0]), "=r"(r[1]), "=r"(r[2]), "=r"(r[3]) : "r"(addr));
}
__device__ __forceinline__ void mma_f16(float (&d)[4], const uint32_t (&a)[4],
                                        uint32_t b0, uint32_t b1) {
    asm volatile(
        "mma.sync.aligned.m16n8k16.row.col.f32.f16.f16.f32 "
        "{%0,%1,%2,%3}, {%4,%5,%6,%7}, {%8,%9}, {%0,%1,%2,%3};"
        : "+f"(d[0]), "+f"(d[1]), "+f"(d[2]), "+f"(d[3])
        : "r"(a[0]), "r"(a[1]), "r"(a[2]), "r"(a[3]), "r"(b0), "r"(b1));
}

__device__ __forceinline__ void store2(__half* C, long off, float v0, float v1) {
    *reinterpret_cast<__half2*>(C + off) =
        __halves2half2(__float2half_rn(v0), __float2half_rn(v1));
}
__device__ __forceinline__ void store2(float* C, long off, float v0, float v1) {
    *reinterpret_cast<float2*>(C + off) = make_float2(v0, v1);
}

template <int K, bool RELU, typename TOUT>
__global__ void __launch_bounds__(NTHREADS, 2)
gemm_f16(const __half* __restrict__ A,     // [M,K] row-major
         const __half* __restrict__ W,     // [N,K] row-major
         const float* __restrict__ bias,   // [N]
         TOUT* __restrict__ C,             // [M,N]
         int Nn)
{
    extern __shared__ char smem[];
    const uint32_t sb = s2u(smem);

    const int tid  = threadIdx.x;
    const int lane = tid & 31;
    const int wid  = tid >> 5;
    const int wr   = wid >> 2;   // 0..1 : 64-row slab
    const int wc   = wid & 3;    // 0..3 : 32-col slab

    const long bm = (long)blockIdx.y * BM;
    const long bn = (long)blockIdx.x * BN;
    constexpr int nchunk = K / BKH;

    // ---- global->shared mapping: 8 threads/row (16B each), 4 rows/thread ----
    const int lrow = tid >> 3;         // 0..31
    const int lc16 = (tid & 7) * 16;   // byte col in 128B row
    const __half* Abase = A + (bm + lrow) * (long)K + (tid & 7) * 8;
    const __half* Bbase = W + (bn + lrow) * (long)K + (tid & 7) * 8;
    constexpr long rstep = 32L * K;    // 32-row advance (halves)

    uint32_t stoff[4];
    #pragma unroll
    for (int k = 0; k < 4; k++)
        stoff[k] = SWZ((uint32_t)((lrow + 32 * k) * 128 + lc16));

    // ---- ldmatrix address components ----
    const uint32_t xorv = (uint32_t)(lane & 7) << 4;           // swizzle xor
    uint32_t arow[4], brow[2];
    #pragma unroll
    for (int mt = 0; mt < 4; mt++)
        arow[mt] = (uint32_t)((wr * 64 + mt * 16 + (lane & 15)) * 128);
    #pragma unroll
    for (int p = 0; p < 2; p++)
        brow[p] = (uint32_t)((wc * 32 + p * 16 + (lane & 7) + ((lane >> 4) & 1) * 8) * 128);
    const uint32_t kA16 = ((lane >> 4) & 1) * 16;   // A: k+8 for lanes 16-31
    const uint32_t kB16 = ((lane >> 3) & 1) * 16;   // B: k+8 for lanes 8-15,24-31

    // per-ks k-byte offsets (post-swizzle xor folded in)
    uint32_t kbA[4], kbB[4];
    #pragma unroll
    for (int ks = 0; ks < 4; ks++) {
        kbA[ks] = ((uint32_t)(ks * 32) + kA16) ^ xorv;
        kbB[ks] = ((uint32_t)(ks * 32) + kB16) ^ xorv;
    }

    float acc[4][4][4];
    #pragma unroll
    for (int mt = 0; mt < 4; mt++)
        #pragma unroll
        for (int nt = 0; nt < 4; nt++)
            #pragma unroll
            for (int r = 0; r < 4; r++) acc[mt][nt][r] = 0.0f;

    #define PRODUCE(slot, kc)                                                   \
        do {                                                                    \
            const uint32_t _as = sb + (slot) * STAGE_BYTES;                     \
            const uint32_t _bs = _as + A_STAGE;                                 \
            const __half* _ap = Abase + (long)(kc) * BKH;                       \
            const __half* _bp = Bbase + (long)(kc) * BKH;                       \
            _Pragma("unroll")                                                   \
            for (int k = 0; k < 4; k++) {                                       \
                cp16(_as + stoff[k], _ap + k * rstep);                          \
                cp16(_bs + stoff[k], _bp + k * rstep);                          \
            }                                                                   \
            asm volatile("cp.async.commit_group;");                             \
        } while (0)

    // prologue: chunk 0 (plus the CTA's 512B bias slice, same commit group
    // so all wait_group counts downstream are unchanged), then chunk 1.
    {
        const uint32_t _as = sb;
        const uint32_t _bs = sb + A_STAGE;
        #pragma unroll
        for (int k = 0; k < 4; k++) {
            cp16(_as + stoff[k], Abase + k * rstep);
            cp16(_bs + stoff[k], Bbase + k * rstep);
        }
        if (tid < 32) cp16(sb + BIAS_SMEM + tid * 16, bias + bn + tid * 4);
        asm volatile("cp.async.commit_group;");
    }
    PRODUCE(1, 1);

    int slot = 0, pslot = 2;
    #pragma unroll 3
    for (int i = 0; i < nchunk; i++) {
        if (i + 2 < nchunk) {
            PRODUCE(pslot, i + 2);
            asm volatile("cp.async.wait_group 2;");
        } else if (i + 1 < nchunk) {
            asm volatile("cp.async.wait_group 1;");
        } else {
            asm volatile("cp.async.wait_group 0;");
        }
        __syncthreads();

        const uint32_t stA = sb + slot * STAGE_BYTES;
        const uint32_t stB = stA + A_STAGE;

        // B-fragment double buffer: prefetch ks+1's B during ks's HMMA block.
        uint32_t bf[2][2][4];
        ldsm4(bf[0][0], stB + brow[0] + kbB[0]);
        ldsm4(bf[0][1], stB + brow[1] + kbB[0]);

        #pragma unroll
        for (int ks = 0; ks < 4; ks++) {
            const int cur = ks & 1;
            const int nxt = cur ^ 1;
            uint32_t af[4][4];
            #pragma unroll
            for (int mt = 0; mt < 4; mt++)
                ldsm4(af[mt], stA + arow[mt] + kbA[ks]);
            if (ks < 3) {
                ldsm4(bf[nxt][0], stB + brow[0] + kbB[ks + 1]);
                ldsm4(bf[nxt][1], stB + brow[1] + kbB[ks + 1]);
            }
            #pragma unroll
            for (int mt = 0; mt < 4; mt++)
                #pragma unroll
                for (int nt = 0; nt < 4; nt++)
                    mma_f16(acc[mt][nt], af[mt],
                            bf[cur][nt >> 1][(nt & 1) * 2],
                            bf[cur][nt >> 1][(nt & 1) * 2 + 1]);
        }
        __syncthreads();
        slot  = (slot  == NSTAGE - 1) ? 0 : slot + 1;
        pslot = (pslot == NSTAGE - 1) ? 0 : pslot + 1;
    }
    #undef PRODUCE

    // ---- epilogue: bias from smem (arrived with chunk-0 group) ----
    const float* bsm = reinterpret_cast<const float*>(smem + BIAS_SMEM);
    const int gid = lane >> 2;     // row in 8-row group
    const int tin = lane & 3;      // column pair
    #pragma unroll
    for (int nt = 0; nt < 4; nt++) {
        const int  nl = wc * 32 + nt * 8 + tin * 2;   // local col in [0,128)
        const long n0 = bn + nl;
        const float bv0 = bsm[nl];
        const float bv1 = bsm[nl + 1];
        #pragma unroll
        for (int mt = 0; mt < 4; mt++) {
            const long m0 = bm + wr * 64 + mt * 16 + gid;
            float v0 = acc[mt][nt][0] + bv0;
            float v1 = acc[mt][nt][1] + bv1;
            float v2 = acc[mt][nt][2] + bv0;
            float v3 = acc[mt][nt][3] + bv1;
            if (RELU) {
                v0 = fmaxf(v0, 0.0f); v1 = fmaxf(v1, 0.0f);
                v2 = fmaxf(v2, 0.0f); v3 = fmaxf(v3, 0.0f);
            }
            store2(C, m0 * Nn + n0, v0, v1);
            store2(C, (m0 + 8) * Nn + n0, v2, v3);
        }
    }
}

// ---- fused prep: convert 4 tensors fp32->fp16 + bias sum, one launch ----
#define NX  ((int)(M_TOK * 1024 / 16))      // 2097152
#define NW1 (2048 * 1024 / 16)              // 131072
#define NW2 (2048 * 2048 / 16)              // 262144
#define NW3 (1024 * 2048 / 16)              // 131072
#define NTOT (NX + NW1 + NW2 + NW3)         // 2621440

__device__ __forceinline__ void conv16(const float4* __restrict__ in,
                                       __half2* __restrict__ out, int i)
{
    float4 a0 = in[4 * i];
    float4 a1 = in[4 * i + 1];
    float4 a2 = in[4 * i + 2];
    float4 a3 = in[4 * i + 3];
    __half2 o0[4], o1[4];
    o0[0] = __halves2half2(__float2half_rn(a0.x), __float2half_rn(a0.y));
    o0[1] = __halves2half2(__float2half_rn(a0.z), __float2half_rn(a0.w));
    o0[2] = __halves2half2(__float2half_rn(a1.x), __float2half_rn(a1.y));
    o0[3] = __halves2half2(__float2half_rn(a1.z), __float2half_rn(a1.w));
    o1[0] = __halves2half2(__float2half_rn(a2.x), __float2half_rn(a2.y));
    o1[1] = __halves2half2(__float2half_rn(a2.z), __float2half_rn(a2.w));
    o1[2] = __halves2half2(__float2half_rn(a3.x), __float2half_rn(a3.y));
    o1[3] = __halves2half2(__float2half_rn(a3.z), __float2half_rn(a3.w));
    *reinterpret_cast<uint4*>(out + 8 * i)     = *reinterpret_cast<uint4*>(o0);
    *reinterpret_cast<uint4*>(out + 8 * i + 4) = *reinterpret_cast<uint4*>(o1);
}

__global__ void prep_kernel(const float4* __restrict__ x,   __half2* __restrict__ xh,
                            const float4* __restrict__ w1f, __half2* __restrict__ w1h,
                            const float4* __restrict__ w2f, __half2* __restrict__ w2h,
                            const float4* __restrict__ w3f, __half2* __restrict__ w3h,
                            const float* __restrict__ bih,  const float* __restrict__ bhh,
                            float* __restrict__ bsum)
{
    const int gtid = blockIdx.x * blockDim.x + threadIdx.x;
    if (gtid < 2048) bsum[gtid] = bih[gtid] + bhh[gtid];

    const int stride = gridDim.x * blockDim.x;
    for (int i = gtid; i < NTOT; i += stride) {
        if (i < NX) {
            conv16(x, xh, i);
        } else if (i < NX + NW1) {
            conv16(w1f, w1h, i - NX);
        } else if (i < NX + NW1 + NW2) {
            conv16(w2f, w2h, i - NX - NW1);
        } else {
            conv16(w3f, w3h, i - NX - NW1 - NW2);
        }
    }
}

extern "C" void kernel_launch(void* const* d_in, const int* in_sizes, int n_in,
                              void* d_out, int out_size)
{
    const float* x       = (const float*)d_in[0];
    const float* W_init  = (const float*)d_in[1];
    const float* b_init  = (const float*)d_in[2];
    const float* W_ih    = (const float*)d_in[3];
    const float* b_ih    = (const float*)d_in[4];
    const float* b_hh    = (const float*)d_in[5];
    const float* W_final = (const float*)d_in[6];
    const float* b_final = (const float*)d_in[7];
    float* y = (float*)d_out;

    __half *xh, *hbuf, *mbuf, *w1, *w2, *w3;
    float* bsum;
    cudaGetSymbolAddress((void**)&xh,   g_xh);
    cudaGetSymbolAddress((void**)&hbuf, g_h);
    cudaGetSymbolAddress((void**)&mbuf, g_mid);
    cudaGetSymbolAddress((void**)&w1,   g_w1);
    cudaGetSymbolAddress((void**)&w2,   g_w2);
    cudaGetSymbolAddress((void**)&w3,   g_w3);
    cudaGetSymbolAddress((void**)&bsum, g_bsum);

    cudaFuncSetAttribute(gemm_f16<1024, true, __half>,
                         cudaFuncAttributeMaxDynamicSharedMemorySize, SMEM_TOTAL);
    cudaFuncSetAttribute(gemm_f16<2048, true, __half>,
                         cudaFuncAttributeMaxDynamicSharedMemorySize, SMEM_TOTAL);
    cudaFuncSetAttribute(gemm_f16<2048, false, float>,
                         cudaFuncAttributeMaxDynamicSharedMemorySize, SMEM_TOTAL);

    // one fused prep launch (grid-stride, wider grid for latency hiding)
    prep_kernel<<<4096, 256>>>((const float4*)x,       (__half2*)xh,
                               (const float4*)W_init,  (__half2*)w1,
                               (const float4*)W_ih,    (__half2*)w2,
                               (const float4*)W_final, (__half2*)w3,
                               b_ih, b_hh, bsum);

    const dim3 block(NTHREADS, 1, 1);
    const dim3 grid12(2048 / BN, M_TOK / BM, 1);   // 16 x 256
    const dim3 grid3 (1024 / BN, M_TOK / BM, 1);   //  8 x 256

    gemm_f16<1024, true, __half><<<grid12, block, SMEM_TOTAL>>>(
        xh, w1, b_init, hbuf, 2048);
    gemm_f16<2048, true, __half><<<grid12, block, SMEM_TOTAL>>>(
        hbuf, w2, bsum, mbuf, 2048);
    gemm_f16<2048, false, float><<<grid3, block, SMEM_TOTAL>>>(
        mbuf, w3, b_final, y, 1024);
}

// round 17
// speedup vs baseline: 1.5796x; 1.0124x over previous
#include <cuda_runtime.h>
#include <cuda_fp16.h>
#include <cstdint>
#include <cstddef>

// ---------------------------------------------------------------------------
// RNNQNetworkZeroState, sm_103. fp16 m16n8k16 mma.sync, fp32 accumulate.
//   prep:  ONE fused kernel: {x,W1,W2,W3} fp32->fp16 (rn) + bsum=b_ih+b_hh
//   GEMM1: xh[M,1024]  @ W1h^T + b_init -> relu -> g_h   (half)
//   GEMM2: g_h[M,2048] @ W2h^T + bsum   -> relu -> g_mid (half)
//   GEMM3: g_mid       @ W3h^T + b_final -> out (float)
// GEMM: tile 128x128 (8 warps, 64x32 warp tiles, 2 CTAs/SM), BK=64 halves,
// 3-stage cp.async pipeline, R4 ordering, B-fragment double buffering,
// K templated, bias staged via smem. New this round: smem-staged COALESCED
// epilogue (fragment-scatter writes to padded smem, then warp-contiguous
// STG.128) -- replaces 256 L1 wavefronts/warp of scattered 4B stores.
// ---------------------------------------------------------------------------

#define BM 128
#define BN 128
#define BKH 64                 // halves per k-chunk = 128 bytes/row
#define NSTAGE 3
#define A_STAGE 16384          // 128 rows x 128 B
#define B_STAGE 16384
#define STAGE_BYTES (A_STAGE + B_STAGE)
#define BIAS_SMEM (NSTAGE * STAGE_BYTES)    // 512B bias slice after stages
#define SMEM_TOTAL (BIAS_SMEM + 512)        // 98816 B
#define NTHREADS 256

// epilogue staging row strides (padded for bank-conflict-free access)
#define SROW_H 272             // 128 halves (256B) + 16B pad
#define SROW_F 528             // 128 floats (512B) + 16B pad

static constexpr size_t M_TOK = 32768;

// Scratch (allocation-free rule: __device__ globals).
__device__ __align__(16) __half g_xh  [M_TOK * 1024];
__device__ __align__(16) __half g_h   [M_TOK * 2048];
__device__ __align__(16) __half g_mid [M_TOK * 2048];
__device__ __align__(16) __half g_w1  [2048 * 1024];
__device__ __align__(16) __half g_w2  [2048 * 2048];
__device__ __align__(16) __half g_w3  [1024 * 2048];
__device__ __align__(16) float  g_bsum[2048];

#define SWZ(o) ((o) ^ (((o) >> 3) & 0x70))

__device__ __forceinline__ uint32_t s2u(const void* p) {
    uint32_t a;
    asm("{ .reg .u64 t; cvta.to.shared.u64 t, %1; cvt.u32.u64 %0, t; }"
        : "=r"(a) : "l"(p));
    return a;
}
__device__ __forceinline__ void cp16(uint32_t s, const void* g) {
    asm volatile("cp.async.cg.shared.global [%0], [%1], 16;" :: "r"(s), "l"(g));
}
__device__ __forceinline__ void ldsm4(uint32_t (&r)[4], uint32_t addr) {
    asm volatile("ldmatrix.sync.aligned.m8n8.x4.shared.b16 {%0,%1,%2,%3}, [%4];"
                 : "=r"(r[0]), "=r"(r[1]), "=r"(r[2]), "=r"(r[3]) : "r"(addr));
}
__device__ __forceinline__ void mma_f16(float (&d)[4], const uint32_t (&a)[4],
                                        uint32_t b0, uint32_t b1) {
    asm volatile(
        "mma.sync.aligned.m16n8k16.row.col.f32.f16.f16.f32 "
        "{%0,%1,%2,%3}, {%4,%5,%6,%7}, {%8,%9}, {%0,%1,%2,%3};"
        : "+f"(d[0]), "+f"(d[1]), "+f"(d[2]), "+f"(d[3])
        : "r"(a[0]), "r"(a[1]), "r"(a[2]), "r"(a[3]), "r"(b0), "r"(b1));
}

template <int K, bool RELU, typename TOUT>
__global__ void __launch_bounds__(NTHREADS, 2)
gemm_f16(const __half* __restrict__ A,     // [M,K] row-major
         const __half* __restrict__ W,     // [N,K] row-major
         const float* __restrict__ bias,   // [N]
         TOUT* __restrict__ C,             // [M,N]
         int Nn)
{
    extern __shared__ char smem[];
    const uint32_t sb = s2u(smem);

    const int tid  = threadIdx.x;
    const int lane = tid & 31;
    const int wid  = tid >> 5;
    const int wr   = wid >> 2;   // 0..1 : 64-row slab
    const int wc   = wid & 3;    // 0..3 : 32-col slab

    const long bm = (long)blockIdx.y * BM;
    const long bn = (long)blockIdx.x * BN;
    constexpr int nchunk = K / BKH;

    // ---- global->shared mapping: 8 threads/row (16B each), 4 rows/thread ----
    const int lrow = tid >> 3;         // 0..31
    const int lc16 = (tid & 7) * 16;   // byte col in 128B row
    const __half* Abase = A + (bm + lrow) * (long)K + (tid & 7) * 8;
    const __half* Bbase = W + (bn + lrow) * (long)K + (tid & 7) * 8;
    constexpr long rstep = 32L * K;    // 32-row advance (halves)

    uint32_t stoff[4];
    #pragma unroll
    for (int k = 0; k < 4; k++)
        stoff[k] = SWZ((uint32_t)((lrow + 32 * k) * 128 + lc16));

    // ---- ldmatrix address components ----
    const uint32_t xorv = (uint32_t)(lane & 7) << 4;           // swizzle xor
    uint32_t arow[4], brow[2];
    #pragma unroll
    for (int mt = 0; mt < 4; mt++)
        arow[mt] = (uint32_t)((wr * 64 + mt * 16 + (lane & 15)) * 128);
    #pragma unroll
    for (int p = 0; p < 2; p++)
        brow[p] = (uint32_t)((wc * 32 + p * 16 + (lane & 7) + ((lane >> 4) & 1) * 8) * 128);
    const uint32_t kA16 = ((lane >> 4) & 1) * 16;   // A: k+8 for lanes 16-31
    const uint32_t kB16 = ((lane >> 3) & 1) * 16;   // B: k+8 for lanes 8-15,24-31

    // per-ks k-byte offsets (post-swizzle xor folded in)
    uint32_t kbA[4], kbB[4];
    #pragma unroll
    for (int ks = 0; ks < 4; ks++) {
        kbA[ks] = ((uint32_t)(ks * 32) + kA16) ^ xorv;
        kbB[ks] = ((uint32_t)(ks * 32) + kB16) ^ xorv;
    }

    float acc[4][4][4];
    #pragma unroll
    for (int mt = 0; mt < 4; mt++)
        #pragma unroll
        for (int nt = 0; nt < 4; nt++)
            #pragma unroll
            for (int r = 0; r < 4; r++) acc[mt][nt][r] = 0.0f;

    #define PRODUCE(slot, kc)                                                   \
        do {                                                                    \
            const uint32_t _as = sb + (slot) * STAGE_BYTES;                     \
            const uint32_t _bs = _as + A_STAGE;                                 \
            const __half* _ap = Abase + (long)(kc) * BKH;                       \
            const __half* _bp = Bbase + (long)(kc) * BKH;                       \
            _Pragma("unroll")                                                   \
            for (int k = 0; k < 4; k++) {                                       \
                cp16(_as + stoff[k], _ap + k * rstep);                          \
                cp16(_bs + stoff[k], _bp + k * rstep);                          \
            }                                                                   \
            asm volatile("cp.async.commit_group;");                             \
        } while (0)

    // prologue: chunk 0 (plus the CTA's 512B bias slice, same commit group
    // so all wait_group counts downstream are unchanged), then chunk 1.
    {
        const uint32_t _as = sb;
        const uint32_t _bs = sb + A_STAGE;
        #pragma unroll
        for (int k = 0; k < 4; k++) {
            cp16(_as + stoff[k], Abase + k * rstep);
            cp16(_bs + stoff[k], Bbase + k * rstep);
        }
        if (tid < 32) cp16(sb + BIAS_SMEM + tid * 16, bias + bn + tid * 4);
        asm volatile("cp.async.commit_group;");
    }
    PRODUCE(1, 1);

    int slot = 0, pslot = 2;
    #pragma unroll 3
    for (int i = 0; i < nchunk; i++) {
        if (i + 2 < nchunk) {
            PRODUCE(pslot, i + 2);
            asm volatile("cp.async.wait_group 2;");
        } else if (i + 1 < nchunk) {
            asm volatile("cp.async.wait_group 1;");
        } else {
            asm volatile("cp.async.wait_group 0;");
        }
        __syncthreads();

        const uint32_t stA = sb + slot * STAGE_BYTES;
        const uint32_t stB = stA + A_STAGE;

        // B-fragment double buffer: prefetch ks+1's B during ks's HMMA block.
        uint32_t bf[2][2][4];
        ldsm4(bf[0][0], stB + brow[0] + kbB[0]);
        ldsm4(bf[0][1], stB + brow[1] + kbB[0]);

        #pragma unroll
        for (int ks = 0; ks < 4; ks++) {
            const int cur = ks & 1;
            const int nxt = cur ^ 1;
            uint32_t af[4][4];
            #pragma unroll
            for (int mt = 0; mt < 4; mt++)
                ldsm4(af[mt], stA + arow[mt] + kbA[ks]);
            if (ks < 3) {
                ldsm4(bf[nxt][0], stB + brow[0] + kbB[ks + 1]);
                ldsm4(bf[nxt][1], stB + brow[1] + kbB[ks + 1]);
            }
            #pragma unroll
            for (int mt = 0; mt < 4; mt++)
                #pragma unroll
                for (int nt = 0; nt < 4; nt++)
                    mma_f16(acc[mt][nt], af[mt],
                            bf[cur][nt >> 1][(nt & 1) * 2],
                            bf[cur][nt >> 1][(nt & 1) * 2 + 1]);
        }
        __syncthreads();
        slot  = (slot  == NSTAGE - 1) ? 0 : slot + 1;
        pslot = (pslot == NSTAGE - 1) ? 0 : pslot + 1;
    }
    #undef PRODUCE

    // ---- epilogue: bias from smem, then smem-staged coalesced stores ----
    // (main loop done; pipeline stage region reused as staging buffer)
    const float* bsm = reinterpret_cast<const float*>(smem + BIAS_SMEM);
    const int gid = lane >> 2;     // row in 8-row group
    const int tin = lane & 3;      // column pair

    // phase 1: fragment-scatter into padded smem (conflict-free / 2-way)
    #pragma unroll
    for (int nt = 0; nt < 4; nt++) {
        const int  nl = wc * 32 + nt * 8 + tin * 2;   // local col in [0,128)
        const float bv0 = bsm[nl];
        const float bv1 = bsm[nl + 1];
        #pragma unroll
        for (int mt = 0; mt < 4; mt++) {
            const int ml = wr * 64 + mt * 16 + gid;   // local row in [0,128)
            float v0 = acc[mt][nt][0] + bv0;
            float v1 = acc[mt][nt][1] + bv1;
            float v2 = acc[mt][nt][2] + bv0;
            float v3 = acc[mt][nt][3] + bv1;
            if (RELU) {
                v0 = fmaxf(v0, 0.0f); v1 = fmaxf(v1, 0.0f);
                v2 = fmaxf(v2, 0.0f); v3 = fmaxf(v3, 0.0f);
            }
            if (sizeof(TOUT) == 2) {
                *reinterpret_cast<__half2*>(smem + ml * SROW_H + nl * 2) =
                    __halves2half2(__float2half_rn(v0), __float2half_rn(v1));
                *reinterpret_cast<__half2*>(smem + (ml + 8) * SROW_H + nl * 2) =
                    __halves2half2(__float2half_rn(v2), __float2half_rn(v3));
            } else {
                *reinterpret_cast<float2*>(smem + ml * SROW_F + nl * 4) =
                    make_float2(v0, v1);
                *reinterpret_cast<float2*>(smem + (ml + 8) * SROW_F + nl * 4) =
                    make_float2(v2, v3);
            }
        }
    }
    __syncthreads();

    // phase 2: warp-contiguous 16B reads + coalesced STG.128
    if (sizeof(TOUT) == 2) {
        // each warp-iter covers 2 full rows (2 x 256B); lanes 0-15 row r0, 16-31 r0+1
        #pragma unroll
        for (int j = 0; j < 8; j++) {
            const int r0  = 2 * (wid + 8 * j);
            const int row = r0 + (lane >> 4);
            uint4 v = *reinterpret_cast<const uint4*>(
                smem + row * SROW_H + (lane & 15) * 16);
            *reinterpret_cast<uint4*>(
                (__half*)C + (bm + row) * (long)Nn + bn + (lane & 15) * 8) = v;
        }
    } else {
        // each warp-iter covers 1 full row (512B); lane = 16B segment
        #pragma unroll
        for (int j = 0; j < 16; j++) {
            const int row = wid + 8 * j;
            uint4 v = *reinterpret_cast<const uint4*>(
                smem + row * SROW_F + lane * 16);
            *reinterpret_cast<uint4*>(
                (float*)C + (bm + row) * (long)Nn + bn + lane * 4) = v;
        }
    }
}

// ---- fused prep: convert 4 tensors fp32->fp16 + bias sum, one launch ----
#define NX  ((int)(M_TOK * 1024 / 16))      // 2097152
#define NW1 (2048 * 1024 / 16)              // 131072
#define NW2 (2048 * 2048 / 16)              // 262144
#define NW3 (1024 * 2048 / 16)              // 131072
#define NTOT (NX + NW1 + NW2 + NW3)         // 2621440

__device__ __forceinline__ void conv16(const float4* __restrict__ in,
                                       __half2* __restrict__ out, int i)
{
    float4 a0 = in[4 * i];
    float4 a1 = in[4 * i + 1];
    float4 a2 = in[4 * i + 2];
    float4 a3 = in[4 * i + 3];
    __half2 o0[4], o1[4];
    o0[0] = __halves2half2(__float2half_rn(a0.x), __float2half_rn(a0.y));
    o0[1] = __halves2half2(__float2half_rn(a0.z), __float2half_rn(a0.w));
    o0[2] = __halves2half2(__float2half_rn(a1.x), __float2half_rn(a1.y));
    o0[3] = __halves2half2(__float2half_rn(a1.z), __float2half_rn(a1.w));
    o1[0] = __halves2half2(__float2half_rn(a2.x), __float2half_rn(a2.y));
    o1[1] = __halves2half2(__float2half_rn(a2.z), __float2half_rn(a2.w));
    o1[2] = __halves2half2(__float2half_rn(a3.x), __float2half_rn(a3.y));
    o1[3] = __halves2half2(__float2half_rn(a3.z), __float2half_rn(a3.w));
    *reinterpret_cast<uint4*>(out + 8 * i)     = *reinterpret_cast<uint4*>(o0);
    *reinterpret_cast<uint4*>(out + 8 * i + 4) = *reinterpret_cast<uint4*>(o1);
}

__global__ void prep_kernel(const float4* __restrict__ x,   __half2* __restrict__ xh,
                            const float4* __restrict__ w1f, __half2* __restrict__ w1h,
                            const float4* __restrict__ w2f, __half2* __restrict__ w2h,
                            const float4* __restrict__ w3f, __half2* __restrict__ w3h,
                            const float* __restrict__ bih,  const float* __restrict__ bhh,
                            float* __restrict__ bsum)
{
    const int gtid = blockIdx.x * blockDim.x + threadIdx.x;
    if (gtid < 2048) bsum[gtid] = bih[gtid] + bhh[gtid];

    const int stride = gridDim.x * blockDim.x;
    for (int i = gtid; i < NTOT; i += stride) {
        if (i < NX) {
            conv16(x, xh, i);
        } else if (i < NX + NW1) {
            conv16(w1f, w1h, i - NX);
        } else if (i < NX + NW1 + NW2) {
            conv16(w2f, w2h, i - NX - NW1);
        } else {
            conv16(w3f, w3h, i - NX - NW1 - NW2);
        }
    }
}

extern "C" void kernel_launch(void* const* d_in, const int* in_sizes, int n_in,
                              void* d_out, int out_size)
{
    const float* x       = (const float*)d_in[0];
    const float* W_init  = (const float*)d_in[1];
    const float* b_init  = (const float*)d_in[2];
    const float* W_ih    = (const float*)d_in[3];
    const float* b_ih    = (const float*)d_in[4];
    const float* b_hh    = (const float*)d_in[5];
    const float* W_final = (const float*)d_in[6];
    const float* b_final = (const float*)d_in[7];
    float* y = (float*)d_out;

    __half *xh, *hbuf, *mbuf, *w1, *w2, *w3;
    float* bsum;
    cudaGetSymbolAddress((void**)&xh,   g_xh);
    cudaGetSymbolAddress((void**)&hbuf, g_h);
    cudaGetSymbolAddress((void**)&mbuf, g_mid);
    cudaGetSymbolAddress((void**)&w1,   g_w1);
    cudaGetSymbolAddress((void**)&w2,   g_w2);
    cudaGetSymbolAddress((void**)&w3,   g_w3);
    cudaGetSymbolAddress((void**)&bsum, g_bsum);

    cudaFuncSetAttribute(gemm_f16<1024, true, __half>,
                         cudaFuncAttributeMaxDynamicSharedMemorySize, SMEM_TOTAL);
    cudaFuncSetAttribute(gemm_f16<2048, true, __half>,
                         cudaFuncAttributeMaxDynamicSharedMemorySize, SMEM_TOTAL);
    cudaFuncSetAttribute(gemm_f16<2048, false, float>,
                         cudaFuncAttributeMaxDynamicSharedMemorySize, SMEM_TOTAL);

    // one fused prep launch (grid-stride, wide grid for latency hiding)
    prep_kernel<<<4096, 256>>>((const float4*)x,       (__half2*)xh,
                               (const float4*)W_init,  (__half2*)w1,
                               (const float4*)W_ih,    (__half2*)w2,
                               (const float4*)W_final, (__half2*)w3,
                               b_ih, b_hh, bsum);

    const dim3 block(NTHREADS, 1, 1);
    const dim3 grid12(2048 / BN, M_TOK / BM, 1);   // 16 x 256
    const dim3 grid3 (1024 / BN, M_TOK / BM, 1);   //  8 x 256

    gemm_f16<1024, true, __half><<<grid12, block, SMEM_TOTAL>>>(
        xh, w1, b_init, hbuf, 2048);
    gemm_f16<2048, true, __half><<<grid12, block, SMEM_TOTAL>>>(
        hbuf, w2, bsum, mbuf, 2048);
    gemm_f16<2048, false, float><<<grid3, block, SMEM_TOTAL>>>(
        mbuf, w3, b_final, y, 1024);
}